// round 2
// baseline (speedup 1.0000x reference)
#include <cuda_runtime.h>
#include <cuda_bf16.h>
#include <math.h>

#define NN 100000
#define EE 3200000
#define NB 391            // (NN+255)/256

// ---- scratch (device globals; allocation-free) ----
__device__ int    g_deg[NN];     // real-edge in-degree
__device__ float  g_dinv[NN];
__device__ int    g_ofs[NN];     // CSR row begin (exclusive scan of deg)
__device__ int    g_cur[NN];     // fill cursor; == row end after k_fill
__device__ int    g_srcT[EE];
__device__ int    g_dstT[EE];
__device__ int    g_csrc[EE];    // CSR: src ids grouped by dst
__device__ float4 g_xw[NN];      // x @ W1            [N,4]
__device__ float4 g_h2w[NN];     // relu(conv1) @ [Wmu|Wls]  [N,4]
__device__ int    g_bsum[512];
__device__ int    g_is64;

// ---- detect whether edge_index arrived as int64 or int32 ----
__global__ void k_detect(const unsigned int* __restrict__ ei) {
    if (threadIdx.x == 0) {
        int all0 = 1;
        #pragma unroll 1
        for (int i = 0; i < 64; ++i)
            if (ei[2 * i + 1] != 0u) { all0 = 0; break; }
        g_is64 = all0;
    }
}

__global__ void k_init(int n) {
    int i = blockIdx.x * blockDim.x + threadIdx.x;
    if (i < n) g_deg[i] = 0;
}

// ---- decode edges to int32 + degree histogram ----
__global__ void k_edges(const void* __restrict__ ei, int e) {
    int i = blockIdx.x * blockDim.x + threadIdx.x;
    if (i >= e) return;
    int s, d;
    if (g_is64) {
        const long long* p = (const long long*)ei;
        s = (int)p[i];
        d = (int)p[(long long)e + i];
    } else {
        const int* p = (const int*)ei;
        s = p[i];
        d = p[e + i];
    }
    g_srcT[i] = s;
    g_dstT[i] = d;
    atomicAdd(&g_deg[d], 1);
}

// ---- 3-stage exclusive scan of g_deg -> g_ofs ----
__global__ void k_scan1(int n) {
    int i = blockIdx.x * 256 + threadIdx.x;
    int v = (i < n) ? g_deg[i] : 0;
    #pragma unroll
    for (int o = 16; o; o >>= 1) v += __shfl_xor_sync(0xffffffffu, v, o);
    __shared__ int ws[8];
    if ((threadIdx.x & 31) == 0) ws[threadIdx.x >> 5] = v;
    __syncthreads();
    if (threadIdx.x == 0) {
        int s = 0;
        #pragma unroll
        for (int k = 0; k < 8; ++k) s += ws[k];
        g_bsum[blockIdx.x] = s;
    }
}

__global__ void k_scan2(int nb) {
    __shared__ int s[512];
    int t = threadIdx.x;
    int orig = (t < nb) ? g_bsum[t] : 0;
    s[t] = orig;
    __syncthreads();
    for (int off = 1; off < 512; off <<= 1) {
        int v = (t >= off) ? s[t - off] : 0;
        __syncthreads();
        s[t] += v;
        __syncthreads();
    }
    if (t < nb) g_bsum[t] = s[t] - orig;   // exclusive block offsets
}

__global__ void k_scan3(int n) {
    int i = blockIdx.x * 256 + threadIdx.x;
    int warp = threadIdx.x >> 5, lane = threadIdx.x & 31;
    int v = (i < n) ? g_deg[i] : 0;
    int x = v;
    #pragma unroll
    for (int o = 1; o < 32; o <<= 1) {
        int t = __shfl_up_sync(0xffffffffu, x, o);
        if (lane >= o) x += t;
    }
    __shared__ int ws[8], wofs[8];
    if (lane == 31) ws[warp] = x;
    __syncthreads();
    if (threadIdx.x == 0) {
        int run = 0;
        #pragma unroll
        for (int k = 0; k < 8; ++k) { wofs[k] = run; run += ws[k]; }
    }
    __syncthreads();
    if (i < n) {
        int e0 = x - v + wofs[warp] + g_bsum[blockIdx.x];
        g_ofs[i] = e0;
        g_cur[i] = e0;
        g_dinv[i] = rsqrtf((float)(v + 1));   // +1 self loop
    }
}

// ---- CSR fill: place src ids into per-dst slots ----
__global__ void k_fill(int e) {
    int i = blockIdx.x * blockDim.x + threadIdx.x;
    if (i >= e) return;
    int d = g_dstT[i];
    int pos = atomicAdd(&g_cur[d], 1);
    g_csrc[pos] = g_srcT[i];
}

// ---- xw = x @ W1 : one warp per row, HBM-bound ----
__global__ void __launch_bounds__(256) k_gemm(const float* __restrict__ x,
                                              const float* __restrict__ W1, int n) {
    __shared__ float4 Ws[512];
    int t = threadIdx.x;
    const float4* W4 = (const float4*)W1;
    Ws[t]       = W4[t];
    Ws[t + 256] = W4[t + 256];
    __syncthreads();

    int warp = t >> 5, lane = t & 31;
    int row  = blockIdx.x * 8 + warp;
    if (row >= n) return;

    const float4* xr = (const float4*)(x + (size_t)row * 512);
    float4 acc = make_float4(0.f, 0.f, 0.f, 0.f);
    #pragma unroll
    for (int i = 0; i < 4; ++i) {
        float4 xv = __ldg(&xr[i * 32 + lane]);
        int k = i * 128 + lane * 4;
        float4 w0 = Ws[k], w1 = Ws[k + 1], w2 = Ws[k + 2], w3 = Ws[k + 3];
        acc.x += xv.x * w0.x + xv.y * w1.x + xv.z * w2.x + xv.w * w3.x;
        acc.y += xv.x * w0.y + xv.y * w1.y + xv.z * w2.y + xv.w * w3.y;
        acc.z += xv.x * w0.z + xv.y * w1.z + xv.z * w2.z + xv.w * w3.z;
        acc.w += xv.x * w0.w + xv.y * w1.w + xv.z * w2.w + xv.w * w3.w;
    }
    #pragma unroll
    for (int off = 16; off; off >>= 1) {
        acc.x += __shfl_xor_sync(0xffffffffu, acc.x, off);
        acc.y += __shfl_xor_sync(0xffffffffu, acc.y, off);
        acc.z += __shfl_xor_sync(0xffffffffu, acc.z, off);
        acc.w += __shfl_xor_sync(0xffffffffu, acc.w, off);
    }
    if (lane == 0) g_xw[row] = acc;
}

// ---- conv1 gather (warp/node) + fused relu+bias + 4x4 second-layer GEMM ----
__global__ void __launch_bounds__(256) k_conv1(const float* __restrict__ b1,
                                               const float* __restrict__ Wmu,
                                               const float* __restrict__ Wls, int n) {
    int warp = threadIdx.x >> 5, lane = threadIdx.x & 31;
    int node = blockIdx.x * 8 + warp;
    if (node >= n) return;
    int beg = g_ofs[node], end = g_cur[node];
    float4 acc = make_float4(0.f, 0.f, 0.f, 0.f);
    for (int j = beg + lane; j < end; j += 32) {
        int s = g_csrc[j];
        float w = g_dinv[s];               // dinv[dst] factored out of the sum
        float4 v = g_xw[s];
        acc.x += w * v.x; acc.y += w * v.y; acc.z += w * v.z; acc.w += w * v.w;
    }
    #pragma unroll
    for (int o = 16; o; o >>= 1) {
        acc.x += __shfl_xor_sync(0xffffffffu, acc.x, o);
        acc.y += __shfl_xor_sync(0xffffffffu, acc.y, o);
        acc.z += __shfl_xor_sync(0xffffffffu, acc.z, o);
        acc.w += __shfl_xor_sync(0xffffffffu, acc.w, o);
    }
    if (lane == 0) {
        float di = g_dinv[node];
        float sl = di * di;
        float4 xv = g_xw[node];
        float h0 = fmaxf(di * acc.x + sl * xv.x + __ldg(&b1[0]), 0.f);
        float h1 = fmaxf(di * acc.y + sl * xv.y + __ldg(&b1[1]), 0.f);
        float h2 = fmaxf(di * acc.z + sl * xv.z + __ldg(&b1[2]), 0.f);
        float h3 = fmaxf(di * acc.w + sl * xv.w + __ldg(&b1[3]), 0.f);
        float4 o;
        o.x = h0 * __ldg(&Wmu[0]) + h1 * __ldg(&Wmu[2]) + h2 * __ldg(&Wmu[4]) + h3 * __ldg(&Wmu[6]);
        o.y = h0 * __ldg(&Wmu[1]) + h1 * __ldg(&Wmu[3]) + h2 * __ldg(&Wmu[5]) + h3 * __ldg(&Wmu[7]);
        o.z = h0 * __ldg(&Wls[0]) + h1 * __ldg(&Wls[2]) + h2 * __ldg(&Wls[4]) + h3 * __ldg(&Wls[6]);
        o.w = h0 * __ldg(&Wls[1]) + h1 * __ldg(&Wls[3]) + h2 * __ldg(&Wls[5]) + h3 * __ldg(&Wls[7]);
        g_h2w[node] = o;
    }
}

// ---- conv2 gather (warp/node) + fused bias + output store ----
__global__ void __launch_bounds__(256) k_conv2(const float* __restrict__ bmu,
                                               const float* __restrict__ bls,
                                               float* __restrict__ out, int n) {
    int warp = threadIdx.x >> 5, lane = threadIdx.x & 31;
    int node = blockIdx.x * 8 + warp;
    if (node >= n) return;
    int beg = g_ofs[node], end = g_cur[node];
    float4 acc = make_float4(0.f, 0.f, 0.f, 0.f);
    for (int j = beg + lane; j < end; j += 32) {
        int s = g_csrc[j];
        float w = g_dinv[s];
        float4 v = g_h2w[s];
        acc.x += w * v.x; acc.y += w * v.y; acc.z += w * v.z; acc.w += w * v.w;
    }
    #pragma unroll
    for (int o = 16; o; o >>= 1) {
        acc.x += __shfl_xor_sync(0xffffffffu, acc.x, o);
        acc.y += __shfl_xor_sync(0xffffffffu, acc.y, o);
        acc.z += __shfl_xor_sync(0xffffffffu, acc.z, o);
        acc.w += __shfl_xor_sync(0xffffffffu, acc.w, o);
    }
    if (lane == 0) {
        float di = g_dinv[node];
        float sl = di * di;
        float4 hv = g_h2w[node];
        float2 mu, ls;
        mu.x = di * acc.x + sl * hv.x + __ldg(&bmu[0]);
        mu.y = di * acc.y + sl * hv.y + __ldg(&bmu[1]);
        ls.x = di * acc.z + sl * hv.z + __ldg(&bls[0]);
        ls.y = di * acc.w + sl * hv.w + __ldg(&bls[1]);
        ((float2*)out)[node] = mu;                       // mu [N,2]
        ((float2*)(out + 2 * (size_t)n))[node] = ls;     // logstd [N,2]
    }
}

extern "C" void kernel_launch(void* const* d_in, const int* in_sizes, int n_in,
                              void* d_out, int out_size) {
    const float* x   = (const float*)d_in[0];
    const void*  ei  = d_in[1];
    const float* W1  = (const float*)d_in[2];
    const float* b1  = (const float*)d_in[3];
    const float* Wmu = (const float*)d_in[4];
    const float* bmu = (const float*)d_in[5];
    const float* Wls = (const float*)d_in[6];
    const float* bls = (const float*)d_in[7];

    int n = in_sizes[0] / 512;   // 100000
    int e = in_sizes[1] / 2;     // 3200000

    int nb = (n + 255) / 256;    // 391
    int eb = (e + 255) / 256;

    k_detect<<<1, 32>>>((const unsigned int*)ei);
    k_gemm<<<(n + 7) / 8, 256>>>(x, W1, n);   // stream x early; g_xw is tiny & stays in L2
    k_init<<<nb, 256>>>(n);
    k_edges<<<eb, 256>>>(ei, e);
    k_scan1<<<nb, 256>>>(n);
    k_scan2<<<1, 512>>>(nb);
    k_scan3<<<nb, 256>>>(n);
    k_fill<<<eb, 256>>>(e);
    k_conv1<<<(n + 7) / 8, 256>>>(b1, Wmu, Wls, n);
    k_conv2<<<(n + 7) / 8, 256>>>(bmu, bls, (float*)d_out, n);
}

// round 3
// speedup vs baseline: 1.2800x; 1.2800x over previous
#include <cuda_runtime.h>
#include <cuda_bf16.h>
#include <math.h>

#define NN 100000
#define EE 3200000

// ---- scratch (device globals; allocation-free) ----
__device__ int    g_deg[NN];
__device__ float  g_dinv[NN];
__device__ int2   g_edge[EE];    // packed (src, dst)
__device__ float4 g_y[NN];       // dinv[s] * (x @ W1)[s]
__device__ float4 g_z[NN];       // dinv[s] * (relu(conv1) @ [Wmu|Wls])[s]
__device__ float4 g_acc1[NN];
__device__ float4 g_acc2[NN];
__device__ int    g_is64;

// ---- detect int64 vs int32 edge_index (high words all zero => int64) ----
__global__ void k_detect(const unsigned int* __restrict__ ei) {
    if (threadIdx.x == 0) {
        int all0 = 1;
        #pragma unroll 1
        for (int i = 0; i < 64; ++i)
            if (ei[2 * i + 1] != 0u) { all0 = 0; break; }
        g_is64 = all0;
    }
}

// ---- init: zero deg + both accumulators ----
__global__ void k_init(int n) {
    int i = blockIdx.x * blockDim.x + threadIdx.x;
    if (i < n) {
        g_deg[i]  = 0;
        g_acc1[i] = make_float4(0.f, 0.f, 0.f, 0.f);
        g_acc2[i] = make_float4(0.f, 0.f, 0.f, 0.f);
    }
}

// ---- decode edges to packed int2 + degree histogram ----
__global__ void k_edges(const void* __restrict__ ei, int e) {
    int i = blockIdx.x * blockDim.x + threadIdx.x;
    if (i >= e) return;
    int s, d;
    if (g_is64) {
        const long long* p = (const long long*)ei;
        s = (int)__ldg(&p[i]);
        d = (int)__ldg(&p[(long long)e + i]);
    } else {
        const int* p = (const int*)ei;
        s = __ldg(&p[i]);
        d = __ldg(&p[e + i]);
    }
    g_edge[i] = make_int2(s, d);
    atomicAdd(&g_deg[d], 1);
}

__global__ void k_dinv(int n) {
    int i = blockIdx.x * blockDim.x + threadIdx.x;
    if (i < n) g_dinv[i] = rsqrtf((float)(g_deg[i] + 1));   // +1 self loop
}

// ---- y = dinv * (x @ W1): one warp per row, HBM-bound ----
__global__ void __launch_bounds__(256) k_gemm(const float* __restrict__ x,
                                              const float* __restrict__ W1, int n) {
    __shared__ float4 Ws[512];                 // W1 [512,4] as 512 x float4
    int t = threadIdx.x;
    const float4* W4 = (const float4*)W1;
    Ws[t]       = W4[t];
    Ws[t + 256] = W4[t + 256];
    __syncthreads();

    int warp = t >> 5, lane = t & 31;
    int row  = blockIdx.x * 8 + warp;
    if (row >= n) return;

    const float4* xr = (const float4*)(x + (size_t)row * 512);
    float4 acc = make_float4(0.f, 0.f, 0.f, 0.f);
    #pragma unroll
    for (int i = 0; i < 4; ++i) {
        float4 xv = __ldg(&xr[i * 32 + lane]);
        int k = i * 128 + lane * 4;
        float4 w0 = Ws[k], w1 = Ws[k + 1], w2 = Ws[k + 2], w3 = Ws[k + 3];
        acc.x += xv.x * w0.x + xv.y * w1.x + xv.z * w2.x + xv.w * w3.x;
        acc.y += xv.x * w0.y + xv.y * w1.y + xv.z * w2.y + xv.w * w3.y;
        acc.z += xv.x * w0.z + xv.y * w1.z + xv.z * w2.z + xv.w * w3.z;
        acc.w += xv.x * w0.w + xv.y * w1.w + xv.z * w2.w + xv.w * w3.w;
    }
    #pragma unroll
    for (int off = 16; off; off >>= 1) {
        acc.x += __shfl_xor_sync(0xffffffffu, acc.x, off);
        acc.y += __shfl_xor_sync(0xffffffffu, acc.y, off);
        acc.z += __shfl_xor_sync(0xffffffffu, acc.z, off);
        acc.w += __shfl_xor_sync(0xffffffffu, acc.w, off);
    }
    if (lane == 0) {
        float di = g_dinv[row];
        g_y[row] = make_float4(di * acc.x, di * acc.y, di * acc.z, di * acc.w);
    }
}

// ---- conv scatter: 2 edges/thread, 1 random gather + 1 vector RED per edge ----
__global__ void __launch_bounds__(256) k_conv1(int npair, int e) {
    int i = blockIdx.x * blockDim.x + threadIdx.x;
    if (i >= npair) return;
    int4 ed = ((const int4*)g_edge)[i];          // two (s,d) pairs
    float4 v0 = g_y[ed.x];
    float4 v1 = g_y[ed.z];
    atomicAdd(&g_acc1[ed.y], v0);
    atomicAdd(&g_acc1[ed.w], v1);
    if (i == 0 && (e & 1)) {                     // odd tail (not hit: E even)
        int2 t = g_edge[e - 1];
        atomicAdd(&g_acc1[t.y], g_y[t.x]);
    }
}

// ---- finalize conv1: h=relu(dinv*(acc+y)+b1), then z = dinv * (h @ [Wmu|Wls]) ----
__global__ void k_fin1(const float* __restrict__ b1,
                       const float* __restrict__ Wmu,
                       const float* __restrict__ Wls, int n) {
    int i = blockIdx.x * blockDim.x + threadIdx.x;
    if (i >= n) return;
    float di = g_dinv[i];
    float4 a = g_acc1[i];
    float4 y = g_y[i];
    float h0 = fmaxf(di * (a.x + y.x) + __ldg(&b1[0]), 0.f);
    float h1 = fmaxf(di * (a.y + y.y) + __ldg(&b1[1]), 0.f);
    float h2 = fmaxf(di * (a.z + y.z) + __ldg(&b1[2]), 0.f);
    float h3 = fmaxf(di * (a.w + y.w) + __ldg(&b1[3]), 0.f);
    float4 o;   // W_mu, W_ls are [4,2] row-major
    o.x = h0 * __ldg(&Wmu[0]) + h1 * __ldg(&Wmu[2]) + h2 * __ldg(&Wmu[4]) + h3 * __ldg(&Wmu[6]);
    o.y = h0 * __ldg(&Wmu[1]) + h1 * __ldg(&Wmu[3]) + h2 * __ldg(&Wmu[5]) + h3 * __ldg(&Wmu[7]);
    o.z = h0 * __ldg(&Wls[0]) + h1 * __ldg(&Wls[2]) + h2 * __ldg(&Wls[4]) + h3 * __ldg(&Wls[6]);
    o.w = h0 * __ldg(&Wls[1]) + h1 * __ldg(&Wls[3]) + h2 * __ldg(&Wls[5]) + h3 * __ldg(&Wls[7]);
    g_z[i] = make_float4(di * o.x, di * o.y, di * o.z, di * o.w);
}

__global__ void __launch_bounds__(256) k_conv2(int npair, int e) {
    int i = blockIdx.x * blockDim.x + threadIdx.x;
    if (i >= npair) return;
    int4 ed = ((const int4*)g_edge)[i];
    float4 v0 = g_z[ed.x];
    float4 v1 = g_z[ed.z];
    atomicAdd(&g_acc2[ed.y], v0);
    atomicAdd(&g_acc2[ed.w], v1);
    if (i == 0 && (e & 1)) {
        int2 t = g_edge[e - 1];
        atomicAdd(&g_acc2[t.y], g_z[t.x]);
    }
}

// ---- finalize conv2: out = dinv*(acc+z) + bias ----
__global__ void k_fin2(const float* __restrict__ bmu,
                       const float* __restrict__ bls,
                       float* __restrict__ out, int n) {
    int i = blockIdx.x * blockDim.x + threadIdx.x;
    if (i >= n) return;
    float di = g_dinv[i];
    float4 a = g_acc2[i];
    float4 z = g_z[i];
    float2 mu, ls;
    mu.x = di * (a.x + z.x) + __ldg(&bmu[0]);
    mu.y = di * (a.y + z.y) + __ldg(&bmu[1]);
    ls.x = di * (a.z + z.z) + __ldg(&bls[0]);
    ls.y = di * (a.w + z.w) + __ldg(&bls[1]);
    ((float2*)out)[i] = mu;                       // mu [N,2]
    ((float2*)(out + 2 * (size_t)n))[i] = ls;     // logstd [N,2]
}

extern "C" void kernel_launch(void* const* d_in, const int* in_sizes, int n_in,
                              void* d_out, int out_size) {
    const float* x   = (const float*)d_in[0];
    const void*  ei  = d_in[1];
    const float* W1  = (const float*)d_in[2];
    const float* b1  = (const float*)d_in[3];
    const float* Wmu = (const float*)d_in[4];
    const float* bmu = (const float*)d_in[5];
    const float* Wls = (const float*)d_in[6];
    const float* bls = (const float*)d_in[7];

    int n = in_sizes[0] / 512;   // 100000
    int e = in_sizes[1] / 2;     // 3200000

    int nb = (n + 255) / 256;
    int eb = (e + 255) / 256;
    int npair = e / 2;
    int pb = (npair + 255) / 256;

    k_detect<<<1, 32>>>((const unsigned int*)ei);
    k_init<<<nb, 256>>>(n);
    k_edges<<<eb, 256>>>(ei, e);
    k_dinv<<<nb, 256>>>(n);
    k_gemm<<<(n + 7) / 8, 256>>>(x, W1, n);
    k_conv1<<<pb, 256>>>(npair, e);
    k_fin1<<<nb, 256>>>(b1, Wmu, Wls, n);
    k_conv2<<<pb, 256>>>(npair, e);
    k_fin2<<<nb, 256>>>(bmu, bls, (float*)d_out, n);
}